// round 3
// baseline (speedup 1.0000x reference)
#include <cuda_runtime.h>
#include <cstdint>

#define NEGF (-1e30f)
#define EPSF (1e-7f)
#define LN2F (0.69314718055994531f)

constexpr int Bc = 64;
constexpr int Tc = 1024;
constexpr int Cc = 128;
constexpr int Lc = 256;
constexpr int BLANKc = Cc - 1;   // 127
constexpr int NCON = 128;        // consumer threads (alpha compute)
constexpr int NT   = 256;        // + 128 producer threads (prefetch/staging)
constexpr int NBLK = 256;        // 4 time-steps per block: t = 1..1024 (t>=inLen masked)

__device__ __forceinline__ float ex2f_(float x){ float r; asm("ex2.approx.ftz.f32 %0, %1;" : "=f"(r) : "f"(x)); return r; }
__device__ __forceinline__ float lg2f_(float x){ float r; asm("lg2.approx.f32 %0, %1;"    : "=f"(r) : "f"(x)); return r; }

// log2-domain logsumexp2: 1 EX2 + 1 LG2
__device__ __forceinline__ float lse2f(float a, float b){
    float m = fmaxf(a, b), l = fminf(a, b);
    return m + lg2f_(1.0f + ex2f_(l - m));
}

__global__ __launch_bounds__(NT, 1) void ctc_loss_kernel(
    const int*   __restrict__ y_true,        // (B, L)
    const float* __restrict__ y_pred,        // (B, T, C)
    const int*   __restrict__ input_length,  // (B, 1)
    const int*   __restrict__ label_length,  // (B, 1)
    float*       __restrict__ out)           // (B, 1)
{
    const int b   = blockIdx.x;
    const int tid = threadIdx.x;
    const float* __restrict__ yp = y_pred + (size_t)b * Tc * Cc;
    const int*   __restrict__ yt = y_true + b * Lc;
    const int inLen  = input_length[b];
    const int labLen = label_length[b];
    const int Sval   = 2 * labLen + 1;

    __shared__ float  lp[8][Cc];          // 8-deep ring of log2-prob rows (row r -> slot r&7)
    __shared__ float4 halo[2][NCON + 2];  // halo[buf][ctid+2] = alpha[sbase..sbase+3]; slots 0,1 = NEGF
    __shared__ float  res[2];

    if (tid < NCON) {
        // ================= CONSUMER: alpha recurrence =================
        const int  ctid   = tid;
        const int  sbase  = ctid * 4;
        const bool isLast = (ctid == NCON - 1);
        const bool v512   = (512 < Sval);

        // static tables for the 5 pairs this thread touches: label states sl = sbase-5+2p
        int  lab[5]; bool skp[5], vE[5], vL[5];
        #pragma unroll
        for (int p = 0; p < 5; ++p) {
            int sl = sbase - 5 + 2 * p;
            lab[p] = BLANKc; skp[p] = false;
            if (sl >= 1 && sl <= 511) {
                int jj = sl >> 1;
                lab[p] = yt[jj];
                skp[p] = (sl >= 3) && (lab[p] != yt[jj - 1]);
            }
            vE[p] = (unsigned)(sl - 1) < (unsigned)Sval;  // even state sl-1
            vL[p] = (unsigned)sl       < (unsigned)Sval;  // label state sl
        }

        // alpha at t=0 (log2 domain)
        float A0 = NEGF, A1 = NEGF, A2 = NEGF, A3 = NEGF, A4 = NEGF;
        if (ctid == 0) {
            A0 = lg2f_(yp[BLANKc] + EPSF);
            if (labLen > 0) A1 = lg2f_(yp[yt[0]] + EPSF);
        }
        halo[0][ctid + 2] = make_float4(A0, A1, A2, A3);
        if (ctid == 0) {
            float4 n4 = make_float4(NEGF, NEGF, NEGF, NEGF);
            halo[0][0] = n4; halo[0][1] = n4; halo[1][0] = n4; halo[1][1] = n4;
            res[0] = NEGF; res[1] = NEGF;
        }
        __syncthreads();

        for (int j = 0; j < NBLK; ++j) {
            const int t0 = 4 * j;
            // X[q] = alpha[sbase-8+q]
            float4 hA = halo[j & 1][ctid];
            float4 hB = halo[j & 1][ctid + 1];
            float X[12];
            X[0]=hA.x; X[1]=hA.y; X[2]=hA.z; X[3]=hA.w;
            X[4]=hB.x; X[5]=hB.y; X[6]=hB.z; X[7]=hB.w;
            X[8]=A0;   X[9]=A1;   X[10]=A2;  X[11]=A3;

            const float* L1 = lp[(t0 + 1) & 7];
            const float* L2 = lp[(t0 + 2) & 7];
            const float* L3 = lp[(t0 + 3) & 7];
            const float* L4 = lp[(t0 + 4) & 7];
            float lb1 = L1[BLANKc], lb2 = L2[BLANKc], lb3 = L3[BLANKc], lb4 = L4[BLANKc];
            float l1[5], l2[5], l3[5], l4[5];
            #pragma unroll
            for (int p = 0; p < 5; ++p) l1[p] = L1[lab[p]];
            #pragma unroll
            for (int p = 1; p < 5; ++p) l2[p] = L2[lab[p]];
            #pragma unroll
            for (int p = 2; p < 5; ++p) l3[p] = L3[lab[p]];
            #pragma unroll
            for (int p = 3; p < 5; ++p) l4[p] = L4[lab[p]];

            const bool act1 = (t0 + 1 < inLen);
            const bool act2 = (t0 + 2 < inLen);
            const bool act3 = (t0 + 3 < inLen);
            const bool act4 = (t0 + 4 < inLen);

// state 512 (last thread only) — uses X[11] BEFORE pair 4 overwrites it
#define A4UPD(ACT, LB) if (isLast) { float v_ = lse2f(A4, X[11]) + (LB); if ((ACT) && v512) A4 = v_; }
// one (even,label) pair, in-place descending update; shared P = lse2(alpha[e], alpha[e-1])
#define PAIR(P, ACT, LLP, LB) { \
            float P_  = lse2f(X[2*(P)+2], X[2*(P)+1]); \
            float vl_ = lse2f(X[2*(P)+3], skp[P] ? P_ : X[2*(P)+2]) + (LLP); \
            if ((ACT) && vL[P]) X[2*(P)+3] = vl_; \
            float ve_ = P_ + (LB); \
            if ((ACT) && vE[P]) X[2*(P)+2] = ve_; }

            A4UPD(act1, lb1)
            PAIR(4,act1,l1[4],lb1) PAIR(3,act1,l1[3],lb1) PAIR(2,act1,l1[2],lb1) PAIR(1,act1,l1[1],lb1) PAIR(0,act1,l1[0],lb1)
            A4UPD(act2, lb2)
            PAIR(4,act2,l2[4],lb2) PAIR(3,act2,l2[3],lb2) PAIR(2,act2,l2[2],lb2) PAIR(1,act2,l2[1],lb2)
            A4UPD(act3, lb3)
            PAIR(4,act3,l3[4],lb3) PAIR(3,act3,l3[3],lb3) PAIR(2,act3,l3[2],lb3)
            A4UPD(act4, lb4)
            PAIR(4,act4,l4[4],lb4) PAIR(3,act4,l4[3],lb4)
#undef PAIR
#undef A4UPD

            A0 = X[8]; A1 = X[9]; A2 = X[10]; A3 = X[11];
            halo[(j + 1) & 1][ctid + 2] = make_float4(A0, A1, A2, A3);
            __syncthreads();
        }

        // epilogue: gather end states
        const int se = 2 * labLen;
        if (se >= sbase && se < sbase + 4) {
            int k = se - sbase;
            res[0] = (k == 0) ? A0 : (k == 1) ? A1 : (k == 2) ? A2 : A3;
        }
        if (isLast && se == 512) res[0] = A4;
        const int sl2 = se - 1;
        if (labLen > 0 && sl2 >= sbase && sl2 < sbase + 4) {
            int k = sl2 - sbase;
            res[1] = (k == 0) ? A0 : (k == 1) ? A1 : (k == 2) ? A2 : A3;
        }
        __syncthreads();
        if (ctid == 0) out[b] = -LN2F * lse2f(res[0], res[1]);

    } else {
        // ================= PRODUCER: prefetch + log2 staging =================
        const int ptid = tid - NCON;

        // prologue: stage rows 1..4, triple-buffer prefetch rows 5..16
        float q0 = yp[(size_t)1 * Cc + ptid], q1 = yp[(size_t)2 * Cc + ptid];
        float q2 = yp[(size_t)3 * Cc + ptid], q3 = yp[(size_t)4 * Cc + ptid];
        lp[1][ptid] = lg2f_(q0 + EPSF);
        lp[2][ptid] = lg2f_(q1 + EPSF);
        lp[3][ptid] = lg2f_(q2 + EPSF);
        lp[4][ptid] = lg2f_(q3 + EPSF);
        float pA[4], pB[4], pC[4];
        #pragma unroll
        for (int i = 0; i < 4; ++i) {
            pA[i] = yp[(size_t)(5 + i) * Cc + ptid];
            pB[i] = yp[(size_t)(9 + i) * Cc + ptid];
            pC[i] = yp[(size_t)min(13 + i, Tc - 1) * Cc + ptid];
        }
        __syncthreads();

        for (int j = 0; j < NBLK; ++j) {
            const int r0 = 4 * j + 5;     // stage rows r0..r0+3 for the NEXT block
            #pragma unroll
            for (int i = 0; i < 4; ++i) lp[(r0 + i) & 7][ptid] = lg2f_(pA[i] + EPSF);
            #pragma unroll
            for (int i = 0; i < 4; ++i) { pA[i] = pB[i]; pB[i] = pC[i]; }
            #pragma unroll
            for (int i = 0; i < 4; ++i) pC[i] = yp[(size_t)min(4 * j + 17 + i, Tc - 1) * Cc + ptid];
            __syncthreads();
        }
        __syncthreads();  // match consumer epilogue barrier
    }
}

extern "C" void kernel_launch(void* const* d_in, const int* in_sizes, int n_in,
                              void* d_out, int out_size) {
    const int*   y_true       = (const int*)d_in[0];
    const float* y_pred       = (const float*)d_in[1];
    const int*   input_length = (const int*)d_in[2];
    const int*   label_length = (const int*)d_in[3];
    float* out = (float*)d_out;

    ctc_loss_kernel<<<Bc, NT>>>(y_true, y_pred, input_length, label_length, out);
}

// round 5
// speedup vs baseline: 1.3453x; 1.3453x over previous
#include <cuda_runtime.h>
#include <cstdint>

#define NEGF (-1e30f)
#define EPSF (1e-7f)
#define LN2F (0.69314718055994531f)

constexpr int Bc = 64;
constexpr int Tc = 1024;
constexpr int Cc = 128;
constexpr int Lc = 256;
constexpr int BLANKc = Cc - 1;   // 127
constexpr int NCON = 256;        // consumers: one (blank,label) state pair per thread
constexpr int NPROD = 128;       // producers: prefetch + log2 staging
constexpr int NT = NCON + NPROD; // 384
constexpr int NBLK = 512;        // 2 steps per block: t = 1..1024 (t>=inLen keeps old)

__device__ __forceinline__ float ex2f_(float x){ float r; asm("ex2.approx.ftz.f32 %0, %1;" : "=f"(r) : "f"(x)); return r; }
__device__ __forceinline__ float lg2f_(float x){ float r; asm("lg2.approx.f32 %0, %1;"    : "=f"(r) : "f"(x)); return r; }

// log2-domain logsumexp2: 1 EX2 + 1 LG2
__device__ __forceinline__ float lse2f(float a, float b){
    float m = fmaxf(a, b), l = fminf(a, b);
    return m + lg2f_(1.0f + ex2f_(l - m));
}

__global__ __launch_bounds__(NT, 1) void ctc_loss_kernel(
    const int*   __restrict__ y_true,        // (B, L)
    const float* __restrict__ y_pred,        // (B, T, C)
    const int*   __restrict__ input_length,  // (B, 1)
    const int*   __restrict__ label_length,  // (B, 1)
    float*       __restrict__ out)           // (B, 1)
{
    const int b   = blockIdx.x;
    const int tid = threadIdx.x;
    const float* __restrict__ yp = y_pred + (size_t)b * Tc * Cc;
    const int*   __restrict__ yt = y_true + b * Lc;
    const int inLen  = input_length[b];
    const int labLen = label_length[b];
    const int Sval   = 2 * labLen + 1;

    __shared__ float  lp[8][Cc];          // ring of log2(p+EPS) rows, row r -> slot r&7
    __shared__ float2 halo[2][NCON + 2];  // [buf][p+2] = (a[2p], a[2p+1]); slots 0,1 = NEGF
    __shared__ float  res2[2];

    if (tid < NCON) {
        // ====================== CONSUMER ======================
        const int  p      = tid;            // pair: states 2p (blank), 2p+1 (label yt[p])
        const bool isLast = (p == NCON - 1);

        const int  lab  = yt[p];
        const int  labA = (p >= 1) ? yt[p - 1] : 0;
        const bool skp  = (p >= 1) && (lab  != yt[p - 1]);
        const bool skpA = (p >= 2) && (labA != yt[p - 2]);
        const bool vE   = (2 * p     < Sval);
        const bool vL   = (2 * p + 1 < Sval);
        const bool vEA  = (p >= 1) && (2 * p - 2 < Sval);
        const bool vLA  = (p >= 1) && (2 * p - 1 < Sval);
        const bool v512 = (512 < Sval);

        // t=0 alphas (log2 domain)
        float a0 = NEGF, a1 = NEGF, A2 = NEGF;
        if (p == 0) {
            a0 = lg2f_(yp[BLANKc] + EPSF);
            if (labLen > 0) a1 = lg2f_(yp[lab] + EPSF);
        }

        halo[0][p + 2] = make_float2(a0, a1);
        if (p == 0) {
            float2 nn = make_float2(NEGF, NEGF);
            halo[0][0] = nn; halo[0][1] = nn; halo[1][0] = nn; halo[1][1] = nn;
            res2[0] = NEGF; res2[1] = NEGF;
        }
        __syncthreads();

        for (int j = 0; j < NBLK; ++j) {
            float g1, h0, h1;
            {
                float2 hA = halo[j & 1][p];       // pair p-2 (label only)
                float2 hB = halo[j & 1][p + 1];   // pair p-1
                g1 = hA.y; h0 = hB.x; h1 = hB.y;
            }

            const float* __restrict__ L1 = lp[(2 * j + 1) & 7];
            const float* __restrict__ L2 = lp[(2 * j + 2) & 7];
            const float pb1 = L1[BLANKc], pb2 = L2[BLANKc];
            const float plA = L1[labA];
            const float pl1 = L1[lab],   pl2 = L2[lab];
            const bool act1 = (2 * j + 1 < inLen);
            const bool act2 = (2 * j + 2 < inLen);

            // ---- step t1: redundant pair p-1, own pair p, state 512 ----
            float PA = lse2f(h0, g1);
            float m0 = (act1 && vEA) ? (PA + pb1) : h0;
            float mlv = lse2f(h1, skpA ? PA : h0) + plA;
            float m1 = (act1 && vLA) ? mlv : h1;

            float P  = lse2f(a0, h1);
            float n0 = (act1 && vE) ? (P + pb1) : a0;
            float nlv = lse2f(a1, skp ? P : a0) + pl1;
            float n1 = (act1 && vL) ? nlv : a1;

            float n2 = A2;
            if (isLast) {
                float v = lse2f(A2, a1) + pb1;
                n2 = (act1 && v512) ? v : A2;
            }

            // ---- step t2: own pair p, state 512 ----
            float P2 = lse2f(n0, m1);
            float e2 = P2 + pb2;
            a0 = (act2 && vE) ? e2 : n0;
            float nlv2 = lse2f(n1, skp ? P2 : n0) + pl2;
            a1 = (act2 && vL) ? nlv2 : n1;
            if (isLast) {
                float v = lse2f(n2, n1) + pb2;
                A2 = (act2 && v512) ? v : n2;
            }

            halo[(j + 1) & 1][p + 2] = make_float2(a0, a1);
            __syncthreads();
        }

        // ---- epilogue ----
        const int se = 2 * labLen;
        if (se < 512 && p == (se >> 1)) res2[0] = a0;
        if (se == 512 && isLast)        res2[0] = A2;
        if (labLen > 0 && p == labLen - 1) res2[1] = a1;
        __syncthreads();
        if (p == 0) out[b] = -LN2F * lse2f(res2[0], res2[1]);

    } else {
        // ====================== PRODUCER ======================
        const int q = tid - NCON;   // 0..127

        // prologue: stage rows 1..4; 4-deep prefetch of rows 5..12
        #pragma unroll
        for (int r = 1; r <= 4; ++r) lp[r][q] = lg2f_(yp[(size_t)r * Cc + q] + EPSF);
        float pA0 = yp[(size_t) 5 * Cc + q], pA1 = yp[(size_t) 6 * Cc + q];
        float pB0 = yp[(size_t) 7 * Cc + q], pB1 = yp[(size_t) 8 * Cc + q];
        float pC0 = yp[(size_t) 9 * Cc + q], pC1 = yp[(size_t)10 * Cc + q];
        float pD0 = yp[(size_t)11 * Cc + q], pD1 = yp[(size_t)12 * Cc + q];
        __syncthreads();

        for (int j = 0; j < NBLK; ++j) {
            lp[(2 * j + 5) & 7][q] = lg2f_(pA0 + EPSF);
            lp[(2 * j + 6) & 7][q] = lg2f_(pA1 + EPSF);
            pA0 = pB0; pA1 = pB1;
            pB0 = pC0; pB1 = pC1;
            pC0 = pD0; pC1 = pD1;
            {
                int r0 = min(2 * j + 11, Tc - 1);
                int r1 = min(2 * j + 12, Tc - 1);
                pD0 = yp[(size_t)r0 * Cc + q];
                pD1 = yp[(size_t)r1 * Cc + q];
            }
            __syncthreads();
        }
        __syncthreads();  // match consumer epilogue barrier
    }
}

extern "C" void kernel_launch(void* const* d_in, const int* in_sizes, int n_in,
                              void* d_out, int out_size) {
    const int*   y_true       = (const int*)d_in[0];
    const float* y_pred       = (const float*)d_in[1];
    const int*   input_length = (const int*)d_in[2];
    const int*   label_length = (const int*)d_in[3];
    float* out = (float*)d_out;

    ctc_loss_kernel<<<Bc, NT>>>(y_true, y_pred, input_length, label_length, out);
}